// round 6
// baseline (speedup 1.0000x reference)
#include <cuda_runtime.h>
#include <cuda_fp16.h>
#include <cstdint>

// Problem constants
#define BATCH 32
#define CIN   128
#define COUT  256
#define HH    56
#define WW    56
#define HWPix (HH*WW)          // 3136
#define KTAPS 9
#define KTOT  (CIN*KTAPS)      // 1152

// conv smem: fp16 tiles, pitch 272B (256B data + 16B pad, ldmatrix conflict-free)
#define PITCH 272
#define ASZ   (128*PITCH)      // 34816
#define BSZ   (256*PITCH)      // 69632
#define STAGE (ASZ+BSZ)        // 104448
#define SMEM_TOTAL (2*STAGE)   // 208896

// Scratch (allocation-free rule: __device__ globals)
__device__ __align__(128) __half g_xh[(size_t)BATCH * HWPix * CIN];   // NHWC fp16
__device__ __align__(128) __half g_wh[(size_t)COUT * KTOT];           // [n][tap][cin]

// ---------------------------------------------------------------------------
// Kernel 1: x fp32 NCHW -> fp16 NHWC. Thread per (pixel, 32-channel group).
// ---------------------------------------------------------------------------
__global__ void convert_x_kernel(const float* __restrict__ x) {
    int idx = blockIdx.x * blockDim.x + threadIdx.x;   // 0 .. 401407
    int pix = idx >> 2;
    int c0  = (idx & 3) << 5;
    int b   = pix / HWPix;
    int hw  = pix - b * HWPix;
    const float* xb = x + (size_t)b * CIN * HWPix + (size_t)c0 * HWPix + hw;
    __half* dst = g_xh + (size_t)pix * CIN + c0;
#pragma unroll
    for (int j = 0; j < 4; j++) {           // 4 x int4 = 64B = 32 fp16
        uint32_t pk[4];
#pragma unroll
        for (int jj = 0; jj < 4; jj++) {
            int c = j * 8 + jj * 2;
            __half h0 = __float2half_rn(xb[(size_t)c * HWPix]);
            __half h1 = __float2half_rn(xb[(size_t)(c + 1) * HWPix]);
            __half2 h2 = __halves2half2(h0, h1);
            pk[jj] = *(uint32_t*)&h2;
        }
        *(int4*)(dst + j * 8) = make_int4((int)pk[0], (int)pk[1], (int)pk[2], (int)pk[3]);
    }
}

// ---------------------------------------------------------------------------
// Kernel 2: weight fp32 OIHW -> fp16 [n][tap][cin]. Thread per (n, c).
// ---------------------------------------------------------------------------
__global__ void convert_w_kernel(const float* __restrict__ w) {
    int t = blockIdx.x * blockDim.x + threadIdx.x;     // 0 .. 32767
    int n = t >> 7;
    int c = t & 127;
    const float* src = w + (size_t)(n * CIN + c) * KTAPS;
    __half* dstb = g_wh + (size_t)n * KTOT + c;
#pragma unroll
    for (int tap = 0; tap < KTAPS; tap++)
        dstb[tap * CIN] = __float2half_rn(src[tap]);
}

// ---------------------------------------------------------------------------
// Kernel 3: implicit-GEMM conv via mma.sync.m16n8k16.f16 (fp32 accumulate).
// CTA: 512 threads (16 warps, 4Mx4N), tile M=128 pixels x N=256 channels.
// cp.async double-buffered over the 9 taps; ldmatrix fragment loads.
// ---------------------------------------------------------------------------
__device__ __forceinline__ void mma_f16(float* c, const int* a, int b0, int b1) {
    asm volatile(
        "mma.sync.aligned.m16n8k16.row.col.f32.f16.f16.f32 "
        "{%0,%1,%2,%3}, {%4,%5,%6,%7}, {%8,%9}, {%0,%1,%2,%3};\n"
        : "+f"(c[0]), "+f"(c[1]), "+f"(c[2]), "+f"(c[3])
        : "r"(a[0]), "r"(a[1]), "r"(a[2]), "r"(a[3]), "r"(b0), "r"(b1));
}

#define CPA16(dst, src, sz) \
    asm volatile("cp.async.cg.shared.global [%0], [%1], 16, %2;\n" \
                 :: "r"(dst), "l"(src), "r"(sz))
#define CPA_COMMIT() asm volatile("cp.async.commit_group;\n")

__global__ void __launch_bounds__(512, 1)
conv_mma_kernel(const float* __restrict__ tbias,
                const int*   __restrict__ nshift,
                const int*   __restrict__ amin,
                const int*   __restrict__ amax,
                float*       __restrict__ out) {
    extern __shared__ __align__(16) int8_t smem[];
    const uint32_t smem_u32 = (uint32_t)__cvta_generic_to_shared(smem);

    const int tid  = threadIdx.x;
    const int lane = tid & 31;
    const int warp = tid >> 5;
    const int warpM = warp >> 2;         // 0..3 -> 32 M-rows each
    const int warpN = warp & 3;          // 0..3 -> 64 N-cols each
    const int g   = lane >> 2;
    const int tig = lane & 3;

    const int m0 = blockIdx.x * 128;     // global pixel base (may span batch)

    // A loader invariants: row = tid>>2 (0..127), quarter = tid&3 (64B each)
    const int ar = tid >> 2, aq = tid & 3;
    const int ap = m0 + ar;
    const int ab = ap / HWPix;
    const int ahw = ap - ab * HWPix;
    const int ah  = ahw / WW;
    const int aw  = ahw - ah * WW;
    // B loader: row = tid>>1 (0..255), half = tid&1 (128B each)
    const int br = tid >> 1, bh = tid & 1;
    const __half* wsrc_base = g_wh + (size_t)br * KTOT + bh * 64;  // 64 fp16 = 128B

    float acc[2][8][4];
#pragma unroll
    for (int i = 0; i < 2; i++)
#pragma unroll
        for (int j = 0; j < 8; j++)
#pragma unroll
            for (int k = 0; k < 4; k++) acc[i][j][k] = 0.0f;

    auto load_tap = [&](int tap, int buf) {
        const int dh = tap / 3 - 1;
        const int dw = tap % 3 - 1;
        // A slab: 128 rows x 256B, zero-fill padding via src-size 0
        {
            int hs = ah + dh, ws = aw + dw;
            bool valid = ((unsigned)hs < HH) && ((unsigned)ws < WW);
            int sidx = valid ? (ab * HWPix + hs * WW + ws) : 0;
            const __half* src = g_xh + ((size_t)sidx << 7) + aq * 32;  // 32 fp16 = 64B
            uint32_t dst = smem_u32 + buf * STAGE + ar * PITCH + aq * 64;
            int sz = valid ? 16 : 0;
#pragma unroll
            for (int c = 0; c < 4; c++)
                CPA16(dst + c * 16, (const int8_t*)src + c * 16, sz);
        }
        // B slab: 256 rows x 256B
        {
            const __half* src = wsrc_base + tap * CIN;
            uint32_t dst = smem_u32 + buf * STAGE + ASZ + br * PITCH + bh * 128;
#pragma unroll
            for (int c = 0; c < 8; c++)
                CPA16(dst + c * 16, (const int8_t*)src + c * 16, 16);
        }
        CPA_COMMIT();
    };

    auto compute = [&](int buf) {
        const uint32_t baseA = smem_u32 + buf * STAGE;
        const uint32_t baseB = baseA + ASZ;
#pragma unroll
        for (int kc = 0; kc < 8; kc++) {           // 8 x k16 chunks (32B each)
            int a[2][4];
#pragma unroll
            for (int mi = 0; mi < 2; mi++) {
                int row = warpM * 32 + mi * 16 + (lane & 15);
                int col = kc * 32 + ((lane >> 4) << 4);
                uint32_t addr = baseA + row * PITCH + col;
                asm volatile(
                    "ldmatrix.sync.aligned.m8n8.x4.shared.b16 {%0,%1,%2,%3}, [%4];\n"
                    : "=r"(a[mi][0]), "=r"(a[mi][1]), "=r"(a[mi][2]), "=r"(a[mi][3])
                    : "r"(addr));
            }
#pragma unroll
            for (int tp = 0; tp < 4; tp++) {
                int tile = lane >> 3;
                int tn   = tp * 2 + (tile >> 1);
                int row  = warpN * 64 + tn * 8 + (lane & 7);
                int col  = kc * 32 + ((tile & 1) << 4);
                uint32_t addr = baseB + row * PITCH + col;
                int b0, b1, b2, b3;
                asm volatile(
                    "ldmatrix.sync.aligned.m8n8.x4.shared.b16 {%0,%1,%2,%3}, [%4];\n"
                    : "=r"(b0), "=r"(b1), "=r"(b2), "=r"(b3)
                    : "r"(addr));
                mma_f16(acc[0][tp * 2],     a[0], b0, b1);
                mma_f16(acc[1][tp * 2],     a[1], b0, b1);
                mma_f16(acc[0][tp * 2 + 1], a[0], b2, b3);
                mma_f16(acc[1][tp * 2 + 1], a[1], b2, b3);
            }
        }
    };

    // ---- software pipeline over taps ----
    load_tap(0, 0);
#pragma unroll 1
    for (int tap = 0; tap < KTAPS; tap++) {
        if (tap < KTAPS - 1) {
            load_tap(tap + 1, (tap + 1) & 1);
            asm volatile("cp.async.wait_group 1;\n");
        } else {
            asm volatile("cp.async.wait_group 0;\n");
        }
        __syncthreads();
        compute(tap & 1);
        __syncthreads();
    }

    // ---- epilogue: round-to-int + bias + arithmetic shift + clamp -> float ----
#pragma unroll
    for (int tn = 0; tn < 8; tn++) {
#pragma unroll
        for (int cb = 0; cb < 2; cb++) {
            int ng = warpN * 64 + tn * 8 + 2 * tig + cb;
            int tb = __float2int_rn(__ldg(&tbias[ng]));
            int sh = -__ldg(&nshift[ng]);
            int mn = __ldg(&amin[ng]);
            int mx = __ldg(&amax[ng]);
#pragma unroll
            for (int mi = 0; mi < 2; mi++) {
#pragma unroll
                for (int rh = 0; rh < 2; rh++) {
                    int ml = warpM * 32 + mi * 16 + rh * 8 + g;
                    int p  = m0 + ml;
                    int bo = p / HWPix;
                    int hwo = p - bo * HWPix;
                    int v = __float2int_rn(acc[mi][tn][rh * 2 + cb]);
                    v = (v + tb) >> sh;
                    v = max(mn, min(mx, v));
                    out[((size_t)bo * COUT + ng) * HWPix + hwo] = (float)v;
                }
            }
        }
    }
}

// ---------------------------------------------------------------------------
// Launch
// ---------------------------------------------------------------------------
extern "C" void kernel_launch(void* const* d_in, const int* in_sizes, int n_in,
                              void* d_out, int out_size) {
    const float* x      = (const float*)d_in[0];
    const float* weight = (const float*)d_in[1];
    const float* tbias  = (const float*)d_in[2];
    const int*   nsh    = (const int*)d_in[3];
    const int*   amin   = (const int*)d_in[4];
    const int*   amax   = (const int*)d_in[5];
    float* out = (float*)d_out;

    static int smem_set = 0;
    if (!smem_set) {
        (void)cudaFuncSetAttribute(conv_mma_kernel,
                                   cudaFuncAttributeMaxDynamicSharedMemorySize,
                                   SMEM_TOTAL);
        smem_set = 1;
    }

    convert_x_kernel<<<(BATCH * HWPix * 4) / 256, 256>>>(x);     // 1568 blocks
    convert_w_kernel<<<(COUT * CIN) / 256, 256>>>(weight);       // 128 blocks
    conv_mma_kernel<<<(BATCH * HWPix) / 128, 512, SMEM_TOTAL>>>(tbias, nsh, amin, amax, out);
}

// round 7
// speedup vs baseline: 1.6799x; 1.6799x over previous
#include <cuda_runtime.h>
#include <cstdint>

// Problem constants
#define BATCH 32
#define CIN   128
#define COUT  256
#define HH    56
#define WW    56
#define HWPix (HH*WW)          // 3136
#define KTAPS 9
#define KTOT  (CIN*KTAPS)      // 1152

#define PA 144                 // A smem pitch (bytes), 16B aligned, LDSM conflict-free
#define PB 144                 // B smem pitch
#define ABUF (64*PA)           // 9216
#define BBUF (256*PB)          // 36864
#define BUFSZ (ABUF + BBUF)    // 46080
#define SMEM_TOTAL (2*BUFSZ)   // 92160

// Scratch (allocation-free rule: __device__ globals)
__device__ __align__(128) int8_t g_x8[(size_t)BATCH * HWPix * CIN];   // NHWC int8
__device__ __align__(128) int8_t g_w8[(size_t)COUT * KTOT];           // [n][tap][cin]

// ---------------------------------------------------------------------------
// Kernel 1: merged converts.
//   blocks [0,392): x fp32 NCHW -> int8 NHWC, thread per pixel (coalesced:
//                   warp reads 32 consecutive pixels per channel = 128B lines;
//                   each thread writes its pixel's 128 channels contiguously).
//   blocks [392,520): w fp32 OIHW -> int8 [n][tap][cin], thread per (n,c).
// ---------------------------------------------------------------------------
__global__ void convert_kernel(const float* __restrict__ x,
                               const float* __restrict__ w) {
    if (blockIdx.x < 392) {
        int p  = blockIdx.x * 256 + threadIdx.x;      // 0 .. 100351
        int b  = p / HWPix;
        int hw = p - b * HWPix;
        const float* xb = x + (size_t)b * CIN * HWPix + hw;
        uint32_t pk[32];
#pragma unroll
        for (int c = 0; c < CIN; c += 4) {
            uint32_t v = 0;
#pragma unroll
            for (int k = 0; k < 4; k++) {
                int val = __float2int_rn(xb[(size_t)(c + k) * HWPix]);
                v |= (uint32_t)(val & 0xFF) << (8 * k);
            }
            pk[c >> 2] = v;
        }
        int4* dst = (int4*)(g_x8 + (size_t)p * CIN);
#pragma unroll
        for (int i = 0; i < 8; i++)
            dst[i] = make_int4((int)pk[4*i], (int)pk[4*i+1], (int)pk[4*i+2], (int)pk[4*i+3]);
    } else {
        int t = (blockIdx.x - 392) * 256 + threadIdx.x;  // 0 .. 32767
        int n = t >> 7;
        int c = t & 127;
        const float* src = w + (size_t)(n * CIN + c) * KTAPS;
        int8_t* dstb = g_w8 + (size_t)n * KTOT + c;
#pragma unroll
        for (int tap = 0; tap < KTAPS; tap++) {
            int val = __float2int_rn(src[tap]);
            dstb[tap * CIN] = (int8_t)val;
        }
    }
}

// ---------------------------------------------------------------------------
// Kernel 2: implicit-GEMM conv. CTA tile M=64 x N=256, 256 threads (2Mx4N warps).
// cp.async double-buffered over the 9 taps; ldmatrix fragment loads.
// (Round-3 kernel, verbatim — at the legacy IMMA instruction-rate floor.)
// ---------------------------------------------------------------------------
__device__ __forceinline__ void mma_s8(int* c, const int* a, int b0, int b1) {
    asm volatile(
        "mma.sync.aligned.m16n8k32.row.col.s32.s8.s8.s32 "
        "{%0,%1,%2,%3}, {%4,%5,%6,%7}, {%8,%9}, {%0,%1,%2,%3};\n"
        : "+r"(c[0]), "+r"(c[1]), "+r"(c[2]), "+r"(c[3])
        : "r"(a[0]), "r"(a[1]), "r"(a[2]), "r"(a[3]), "r"(b0), "r"(b1));
}

#define CPA16(dst, src, sz) \
    asm volatile("cp.async.cg.shared.global [%0], [%1], 16, %2;\n" \
                 :: "r"(dst), "l"(src), "r"(sz))
#define CPA_COMMIT() asm volatile("cp.async.commit_group;\n")

__global__ void __launch_bounds__(256, 2)
conv_mma_kernel(const float* __restrict__ tbias,
                const int*   __restrict__ nshift,
                const int*   __restrict__ amin,
                const int*   __restrict__ amax,
                float*       __restrict__ out) {
    extern __shared__ __align__(16) int8_t smem[];
    const uint32_t smem_u32 = (uint32_t)__cvta_generic_to_shared(smem);

    const int tid  = threadIdx.x;
    const int lane = tid & 31;
    const int warp = tid >> 5;
    const int warpM = warp >> 2;         // 0..1 -> 32 M-rows
    const int warpN = warp & 3;          // 0..3 -> 64 N-cols
    const int g   = lane >> 2;
    const int tig = lane & 3;

    const int m0  = blockIdx.x * 64;     // 3136 % 64 == 0 -> tile never spans batch
    const int b   = m0 / HWPix;
    const int hw0 = m0 - b * HWPix;

    // per-thread A-loader invariants: row = tid>>2 (0..63), quarter = tid&3
    const int ar = tid >> 2, aq = tid & 3;
    const int ahw = hw0 + ar;
    const int ah  = ahw / WW;
    const int aw  = ahw - ah * WW;
    // B-loader: one 128B weight row per thread
    const int8_t* wsrc_base = g_w8 + (size_t)tid * KTOT;

    int acc[2][8][4];
#pragma unroll
    for (int i = 0; i < 2; i++)
#pragma unroll
        for (int j = 0; j < 8; j++)
#pragma unroll
            for (int k = 0; k < 4; k++) acc[i][j][k] = 0;

    // ---- tap loader (cp.async into buffer buf) ----
    auto load_tap = [&](int tap, int buf) {
        const int dh = tap / 3 - 1;
        const int dw = tap % 3 - 1;
        // A slab: 64 rows x 128B, zero-fill padding rows via src-size=0
        {
            int hs = ah + dh, ws = aw + dw;
            bool valid = ((unsigned)hs < HH) && ((unsigned)ws < WW);
            int sidx = valid ? (b * HWPix + hs * WW + ws) : 0;
            const int8_t* src = g_x8 + ((size_t)sidx << 7) + aq * 32;
            uint32_t dst = smem_u32 + buf * BUFSZ + ar * PA + aq * 32;
            int sz = valid ? 16 : 0;
            CPA16(dst,      src,      sz);
            CPA16(dst + 16, src + 16, sz);
        }
        // B slab: 256 rows x 128B
        {
            const int8_t* src = wsrc_base + tap * CIN;
            uint32_t dst = smem_u32 + buf * BUFSZ + ABUF + tid * PB;
#pragma unroll
            for (int i = 0; i < 8; i++)
                CPA16(dst + i * 16, src + i * 16, 16);
        }
        CPA_COMMIT();
    };

    // ---- compute one tap from buffer buf ----
    auto compute = [&](int buf) {
        const uint32_t baseA = smem_u32 + buf * BUFSZ;
        const uint32_t baseB = baseA + ABUF;
#pragma unroll
        for (int k0 = 0; k0 < 128; k0 += 32) {
            int a[2][4];
#pragma unroll
            for (int mi = 0; mi < 2; mi++) {
                int row = warpM * 32 + mi * 16 + (lane & 15);
                int col = k0 + ((lane >> 4) << 4);
                uint32_t addr = baseA + row * PA + col;
                asm volatile(
                    "ldmatrix.sync.aligned.m8n8.x4.shared.b16 {%0,%1,%2,%3}, [%4];\n"
                    : "=r"(a[mi][0]), "=r"(a[mi][1]), "=r"(a[mi][2]), "=r"(a[mi][3])
                    : "r"(addr));
            }
#pragma unroll
            for (int tp = 0; tp < 4; tp++) {
                int tile = lane >> 3;
                int tn   = tp * 2 + (tile >> 1);
                int row  = warpN * 64 + tn * 8 + (lane & 7);
                int col  = k0 + ((tile & 1) << 4);
                uint32_t addr = baseB + row * PB + col;
                int b0, b1, b2, b3;
                asm volatile(
                    "ldmatrix.sync.aligned.m8n8.x4.shared.b16 {%0,%1,%2,%3}, [%4];\n"
                    : "=r"(b0), "=r"(b1), "=r"(b2), "=r"(b3)
                    : "r"(addr));
                mma_s8(acc[0][tp * 2],     a[0], b0, b1);
                mma_s8(acc[1][tp * 2],     a[1], b0, b1);
                mma_s8(acc[0][tp * 2 + 1], a[0], b2, b3);
                mma_s8(acc[1][tp * 2 + 1], a[1], b2, b3);
            }
        }
    };

    // ---- software pipeline over taps ----
    load_tap(0, 0);
#pragma unroll 1
    for (int tap = 0; tap < KTAPS; tap++) {
        if (tap < KTAPS - 1) {
            load_tap(tap + 1, (tap + 1) & 1);
            asm volatile("cp.async.wait_group 1;\n");
        } else {
            asm volatile("cp.async.wait_group 0;\n");
        }
        __syncthreads();
        compute(tap & 1);
        __syncthreads();
    }

    // ---- epilogue: bias + arithmetic shift + clamp -> float32 out ----
#pragma unroll
    for (int tn = 0; tn < 8; tn++) {
#pragma unroll
        for (int cb = 0; cb < 2; cb++) {
            int ng = warpN * 64 + tn * 8 + 2 * tig + cb;
            int tb = __float2int_rn(__ldg(&tbias[ng]));
            int sh = -__ldg(&nshift[ng]);
            int mn = __ldg(&amin[ng]);
            int mx = __ldg(&amax[ng]);
            float* rowp = out + ((size_t)b * COUT + ng) * HWPix + hw0;
#pragma unroll
            for (int mi = 0; mi < 2; mi++) {
#pragma unroll
                for (int rh = 0; rh < 2; rh++) {
                    int v = acc[mi][tn][rh * 2 + cb];
                    v = (v + tb) >> sh;
                    v = max(mn, min(mx, v));
                    int ml = warpM * 32 + mi * 16 + rh * 8 + g;
                    rowp[ml] = (float)v;
                }
            }
        }
    }
}

// ---------------------------------------------------------------------------
// Launch
// ---------------------------------------------------------------------------
extern "C" void kernel_launch(void* const* d_in, const int* in_sizes, int n_in,
                              void* d_out, int out_size) {
    const float* x      = (const float*)d_in[0];
    const float* weight = (const float*)d_in[1];
    const float* tbias  = (const float*)d_in[2];
    const int*   nsh    = (const int*)d_in[3];
    const int*   amin   = (const int*)d_in[4];
    const int*   amax   = (const int*)d_in[5];
    float* out = (float*)d_out;

    (void)cudaFuncSetAttribute(conv_mma_kernel,
                               cudaFuncAttributeMaxDynamicSharedMemorySize,
                               SMEM_TOTAL);

    convert_kernel<<<520, 256>>>(x, weight);                             // 392 + 128 blocks
    conv_mma_kernel<<<BATCH * (HWPix / 64), 256, SMEM_TOTAL>>>(tbias, nsh, amin, amax, out);
}

// round 8
// speedup vs baseline: 3.0309x; 1.8042x over previous
#include <cuda_runtime.h>
#include <cstdint>

// Problem constants
#define BATCH 32
#define CIN   128
#define COUT  256
#define HH    56
#define WW    56
#define HWPix (HH*WW)          // 3136
#define KTAPS 9
#define KTOT  (CIN*KTAPS)      // 1152

#define PA 144                 // A smem pitch (bytes), LDSM conflict-free
#define ABUF (64*PA)           // 9216

// Scratch (allocation-free rule: __device__ globals)
__device__ __align__(128) int8_t g_x8[(size_t)BATCH * HWPix * CIN];     // NHWC int8
// Weights in mma-fragment order: [ntile 32][tap 9][kchunk 4][lane 32] x 8B
__device__ __align__(128) int8_t g_wfrag[32 * KTAPS * 4 * 256];         // 294912 B

// ---------------------------------------------------------------------------
// Kernel 1: merged converts.
//   blocks [0,392): x fp32 NCHW -> int8 NHWC, thread per pixel.
//   blocks [392,536): w fp32 OIHW -> fragment-ordered int8 (thread per lane-entry).
// ---------------------------------------------------------------------------
__global__ void convert_kernel(const float* __restrict__ x,
                               const float* __restrict__ w) {
    if (blockIdx.x < 392) {
        int p  = blockIdx.x * 256 + threadIdx.x;      // 0 .. 100351
        int b  = p / HWPix;
        int hw = p - b * HWPix;
        const float* xb = x + (size_t)b * CIN * HWPix + hw;
        uint32_t pk[32];
#pragma unroll
        for (int c = 0; c < CIN; c += 4) {
            uint32_t v = 0;
#pragma unroll
            for (int k = 0; k < 4; k++) {
                int val = __float2int_rn(xb[(size_t)(c + k) * HWPix]);
                v |= (uint32_t)(val & 0xFF) << (8 * k);
            }
            pk[c >> 2] = v;
        }
        int4* dst = (int4*)(g_x8 + (size_t)p * CIN);
#pragma unroll
        for (int i = 0; i < 8; i++)
            dst[i] = make_int4((int)pk[4*i], (int)pk[4*i+1], (int)pk[4*i+2], (int)pk[4*i+3]);
    } else {
        // fragment entry t: [nt][tap][kc][lane]; lane (g = l>>2, tig = l&3) holds
        // bytes W[n = nt*8+g][tap][c = kc*32 + 4*tig + j] (j=0..3) and same with c+16.
        int t = (blockIdx.x - 392) * 256 + threadIdx.x;   // 0 .. 36863
        if (t < 32 * KTAPS * 4 * 32) {
            int nt  = t / (KTAPS * 4 * 32);
            int r   = t - nt * (KTAPS * 4 * 32);
            int tap = r / (4 * 32);
            int r2  = r - tap * (4 * 32);
            int kc  = r2 >> 5;
            int l   = r2 & 31;
            int g   = l >> 2, tig = l & 3;
            int n   = nt * 8 + g;
            uint32_t v0 = 0, v1 = 0;
#pragma unroll
            for (int j = 0; j < 4; j++) {
                int c0 = kc * 32 + 4 * tig + j;
                int val0 = __float2int_rn(w[((size_t)(n * CIN + c0)) * KTAPS + tap]);
                int val1 = __float2int_rn(w[((size_t)(n * CIN + c0 + 16)) * KTAPS + tap]);
                v0 |= (uint32_t)(val0 & 0xFF) << (8 * j);
                v1 |= (uint32_t)(val1 & 0xFF) << (8 * j);
            }
            int2* dst = (int2*)(g_wfrag + (size_t)t * 8);
            *dst = make_int2((int)v0, (int)v1);
        }
    }
}

// ---------------------------------------------------------------------------
// Kernel 2: implicit-GEMM conv. CTA tile M=64 x N=256, 256 threads (2Mx4N warps).
// A: cp.async double-buffered smem + ldmatrix. B: direct coalesced LDG of
// fragment-ordered weights (no smem). One barrier per tap.
// ---------------------------------------------------------------------------
__device__ __forceinline__ void mma_s8(int* c, const int* a, int b0, int b1) {
    asm volatile(
        "mma.sync.aligned.m16n8k32.row.col.s32.s8.s8.s32 "
        "{%0,%1,%2,%3}, {%4,%5,%6,%7}, {%8,%9}, {%0,%1,%2,%3};\n"
        : "+r"(c[0]), "+r"(c[1]), "+r"(c[2]), "+r"(c[3])
        : "r"(a[0]), "r"(a[1]), "r"(a[2]), "r"(a[3]), "r"(b0), "r"(b1));
}

#define CPA16(dst, src, sz) \
    asm volatile("cp.async.cg.shared.global [%0], [%1], 16, %2;\n" \
                 :: "r"(dst), "l"(src), "r"(sz))
#define CPA_COMMIT() asm volatile("cp.async.commit_group;\n")

__global__ void __launch_bounds__(256, 2)
conv_mma_kernel(const float* __restrict__ tbias,
                const int*   __restrict__ nshift,
                const int*   __restrict__ amin,
                const int*   __restrict__ amax,
                float*       __restrict__ out) {
    __shared__ __align__(16) int8_t smA[2 * ABUF];
    const uint32_t smem_u32 = (uint32_t)__cvta_generic_to_shared(smA);

    const int tid  = threadIdx.x;
    const int lane = tid & 31;
    const int warp = tid >> 5;
    const int warpM = warp >> 2;         // 0..1 -> 32 M-rows
    const int warpN = warp & 3;          // 0..3 -> 64 N-cols (8 n8-tiles)
    const int g   = lane >> 2;
    const int tig = lane & 3;

    const int m0  = blockIdx.x * 64;     // 3136 % 64 == 0 -> tile never spans batch
    const int b   = m0 / HWPix;
    const int hw0 = m0 - b * HWPix;

    // A-loader invariants: row = tid>>2 (0..63), quarter = tid&3 (32B each)
    const int ar = tid >> 2, aq = tid & 3;
    const int ahw = hw0 + ar;
    const int ah  = ahw / WW;
    const int aw  = ahw - ah * WW;

    // B fragment base for this warp: tiles warpN*8 .. warpN*8+7
    // layout stride: per nt = KTAPS*4*256 = 9216 B = 1152 int2
    const int2* wfrag = (const int2*)(g_wfrag + (size_t)(warpN * 8) * (KTAPS * 4 * 256))
                        + lane;          // + lane*8B

    int acc[2][8][4];
#pragma unroll
    for (int i = 0; i < 2; i++)
#pragma unroll
        for (int j = 0; j < 8; j++)
#pragma unroll
            for (int k = 0; k < 4; k++) acc[i][j][k] = 0;

    auto load_tapA = [&](int tap, int buf) {
        const int dh = tap / 3 - 1;
        const int dw = tap % 3 - 1;
        int hs = ah + dh, ws = aw + dw;
        bool valid = ((unsigned)hs < HH) && ((unsigned)ws < WW);
        int sidx = valid ? (b * HWPix + hs * WW + ws) : 0;
        const int8_t* src = g_x8 + ((size_t)sidx << 7) + aq * 32;
        uint32_t dst = smem_u32 + buf * ABUF + ar * PA + aq * 32;
        int sz = valid ? 16 : 0;
        CPA16(dst,      src,      sz);
        CPA16(dst + 16, src + 16, sz);
        CPA_COMMIT();
    };

    auto compute = [&](int tap, int buf) {
        const uint32_t baseA = smem_u32 + buf * ABUF;
#pragma unroll
        for (int kc = 0; kc < 4; kc++) {
            int a[2][4];
#pragma unroll
            for (int mi = 0; mi < 2; mi++) {
                int row = warpM * 32 + mi * 16 + (lane & 15);
                int col = kc * 32 + ((lane >> 4) << 4);
                uint32_t addr = baseA + row * PA + col;
                asm volatile(
                    "ldmatrix.sync.aligned.m8n8.x4.shared.b16 {%0,%1,%2,%3}, [%4];\n"
                    : "=r"(a[mi][0]), "=r"(a[mi][1]), "=r"(a[mi][2]), "=r"(a[mi][3])
                    : "r"(addr));
            }
            const int2* wp = wfrag + (size_t)(tap * 4 + kc) * 32;  // [tap][kc] block
#pragma unroll
            for (int tn = 0; tn < 8; tn++) {
                int2 f = __ldg(wp + (size_t)tn * 1152);            // nt stride
                mma_s8(acc[0][tn], a[0], f.x, f.y);
                mma_s8(acc[1][tn], a[1], f.x, f.y);
            }
        }
    };

    // ---- pipeline: one barrier per tap ----
    load_tapA(0, 0);
#pragma unroll 1
    for (int tap = 0; tap < KTAPS; tap++) {
        asm volatile("cp.async.wait_group 0;\n");
        __syncthreads();
        if (tap < KTAPS - 1) load_tapA(tap + 1, (tap + 1) & 1);
        compute(tap, tap & 1);
    }

    // ---- epilogue: bias + arithmetic shift + clamp -> float32 out ----
#pragma unroll
    for (int tn = 0; tn < 8; tn++) {
#pragma unroll
        for (int cb = 0; cb < 2; cb++) {
            int ng = warpN * 64 + tn * 8 + 2 * tig + cb;
            int tb = __float2int_rn(__ldg(&tbias[ng]));
            int sh = -__ldg(&nshift[ng]);
            int mn = __ldg(&amin[ng]);
            int mx = __ldg(&amax[ng]);
            float* rowp = out + ((size_t)b * COUT + ng) * HWPix + hw0;
#pragma unroll
            for (int mi = 0; mi < 2; mi++) {
#pragma unroll
                for (int rh = 0; rh < 2; rh++) {
                    int v = acc[mi][tn][rh * 2 + cb];
                    v = (v + tb) >> sh;
                    v = max(mn, min(mx, v));
                    int ml = warpM * 32 + mi * 16 + rh * 8 + g;
                    rowp[ml] = (float)v;
                }
            }
        }
    }
}

// ---------------------------------------------------------------------------
// Launch
// ---------------------------------------------------------------------------
extern "C" void kernel_launch(void* const* d_in, const int* in_sizes, int n_in,
                              void* d_out, int out_size) {
    const float* x      = (const float*)d_in[0];
    const float* weight = (const float*)d_in[1];
    const float* tbias  = (const float*)d_in[2];
    const int*   nsh    = (const int*)d_in[3];
    const int*   amin   = (const int*)d_in[4];
    const int*   amax   = (const int*)d_in[5];
    float* out = (float*)d_out;

    convert_kernel<<<536, 256>>>(x, weight);                       // 392 + 144 blocks
    conv_mma_kernel<<<BATCH * (HWPix / 64), 256>>>(tbias, nsh, amin, amax, out);
}

// round 9
// speedup vs baseline: 3.0360x; 1.0017x over previous
#include <cuda_runtime.h>
#include <cstdint>

// Problem constants
#define BATCH 32
#define CIN   128
#define COUT  256
#define HH    56
#define WW    56
#define HWPix (HH*WW)          // 3136
#define KTAPS 9
#define KTOT  (CIN*KTAPS)      // 1152

#define PA 144                 // A smem pitch (bytes), LDSM conflict-free
#define ABUF (64*PA)           // 9216
#define SMEMSZ (KTAPS*ABUF)    // 82944 : all 9 tap slabs resident

// Scratch (allocation-free rule: __device__ globals)
__device__ __align__(128) int8_t g_x8[(size_t)BATCH * HWPix * CIN];     // NHWC int8
// Weights in mma-fragment order: [ntile 32][tap 9][kchunk 4][lane 32] x 8B
__device__ __align__(128) int8_t g_wfrag[32 * KTAPS * 4 * 256];         // 294912 B

// ---------------------------------------------------------------------------
// Kernel 1: merged converts.
//   blocks [0,392): x fp32 NCHW -> int8 NHWC, thread per pixel.
//   blocks [392,536): w fp32 OIHW -> fragment-ordered int8.
// ---------------------------------------------------------------------------
__global__ void convert_kernel(const float* __restrict__ x,
                               const float* __restrict__ w) {
    if (blockIdx.x < 392) {
        int p  = blockIdx.x * 256 + threadIdx.x;      // 0 .. 100351
        int b  = p / HWPix;
        int hw = p - b * HWPix;
        const float* xb = x + (size_t)b * CIN * HWPix + hw;
        uint32_t pk[32];
#pragma unroll
        for (int c = 0; c < CIN; c += 4) {
            uint32_t v = 0;
#pragma unroll
            for (int k = 0; k < 4; k++) {
                int val = __float2int_rn(xb[(size_t)(c + k) * HWPix]);
                v |= (uint32_t)(val & 0xFF) << (8 * k);
            }
            pk[c >> 2] = v;
        }
        int4* dst = (int4*)(g_x8 + (size_t)p * CIN);
#pragma unroll
        for (int i = 0; i < 8; i++)
            dst[i] = make_int4((int)pk[4*i], (int)pk[4*i+1], (int)pk[4*i+2], (int)pk[4*i+3]);
    } else {
        // fragment entry t: [nt][tap][kc][lane]; lane (g=l>>2, tig=l&3) holds
        // bytes W[n=nt*8+g][tap][c=kc*32+4*tig+j] (j=0..3) and same with c+16.
        int t = (blockIdx.x - 392) * 256 + threadIdx.x;   // 0 .. 36863
        if (t < 32 * KTAPS * 4 * 32) {
            int nt  = t / (KTAPS * 4 * 32);
            int r   = t - nt * (KTAPS * 4 * 32);
            int tap = r / (4 * 32);
            int r2  = r - tap * (4 * 32);
            int kc  = r2 >> 5;
            int l   = r2 & 31;
            int g   = l >> 2, tig = l & 3;
            int n   = nt * 8 + g;
            uint32_t v0 = 0, v1 = 0;
#pragma unroll
            for (int j = 0; j < 4; j++) {
                int c0 = kc * 32 + 4 * tig + j;
                int val0 = __float2int_rn(w[((size_t)(n * CIN + c0)) * KTAPS + tap]);
                int val1 = __float2int_rn(w[((size_t)(n * CIN + c0 + 16)) * KTAPS + tap]);
                v0 |= (uint32_t)(val0 & 0xFF) << (8 * j);
                v1 |= (uint32_t)(val1 & 0xFF) << (8 * j);
            }
            int2* dst = (int2*)(g_wfrag + (size_t)t * 8);
            *dst = make_int2((int)v0, (int)v1);
        }
    }
}

// ---------------------------------------------------------------------------
// Kernel 2: implicit-GEMM conv. CTA tile M=64 x N=256, 256 threads (2Mx4N warps).
// ALL 9 A-tap slabs loaded up front into resident smem -> zero in-loop barriers.
// B: direct coalesced LDG of fragment-ordered weights (no smem).
// ---------------------------------------------------------------------------
__device__ __forceinline__ void mma_s8(int* c, const int* a, int b0, int b1) {
    asm volatile(
        "mma.sync.aligned.m16n8k32.row.col.s32.s8.s8.s32 "
        "{%0,%1,%2,%3}, {%4,%5,%6,%7}, {%8,%9}, {%0,%1,%2,%3};\n"
        : "+r"(c[0]), "+r"(c[1]), "+r"(c[2]), "+r"(c[3])
        : "r"(a[0]), "r"(a[1]), "r"(a[2]), "r"(a[3]), "r"(b0), "r"(b1));
}

#define CPA16(dst, src, sz) \
    asm volatile("cp.async.cg.shared.global [%0], [%1], 16, %2;\n" \
                 :: "r"(dst), "l"(src), "r"(sz))

__global__ void __launch_bounds__(256, 2)
conv_mma_kernel(const float* __restrict__ tbias,
                const int*   __restrict__ nshift,
                const int*   __restrict__ amin,
                const int*   __restrict__ amax,
                float*       __restrict__ out) {
    extern __shared__ __align__(16) int8_t smA[];
    const uint32_t smem_u32 = (uint32_t)__cvta_generic_to_shared(smA);

    const int tid  = threadIdx.x;
    const int lane = tid & 31;
    const int warp = tid >> 5;
    const int warpM = warp >> 2;         // 0..1 -> 32 M-rows
    const int warpN = warp & 3;          // 0..3 -> 64 N-cols (8 n8-tiles)
    const int g   = lane >> 2;
    const int tig = lane & 3;

    const int m0  = blockIdx.x * 64;     // 3136 % 64 == 0 -> tile never spans batch
    const int b   = m0 / HWPix;
    const int hw0 = m0 - b * HWPix;

    // A-loader invariants: row = tid>>2 (0..63), quarter = tid&3 (32B each)
    const int ar = tid >> 2, aq = tid & 3;
    const int ahw = hw0 + ar;
    const int ah  = ahw / WW;
    const int aw  = ahw - ah * WW;

    // ---- load ALL 9 tap slabs up front (single group, single barrier) ----
#pragma unroll
    for (int tap = 0; tap < KTAPS; tap++) {
        const int dh = tap / 3 - 1;
        const int dw = tap % 3 - 1;
        int hs = ah + dh, ws = aw + dw;
        bool valid = ((unsigned)hs < HH) && ((unsigned)ws < WW);
        int sidx = valid ? (b * HWPix + hs * WW + ws) : 0;
        const int8_t* src = g_x8 + ((size_t)sidx << 7) + aq * 32;
        uint32_t dst = smem_u32 + tap * ABUF + ar * PA + aq * 32;
        int sz = valid ? 16 : 0;
        CPA16(dst,      src,      sz);
        CPA16(dst + 16, src + 16, sz);
    }
    asm volatile("cp.async.commit_group;\n");

    // B fragment base for this warp: tiles warpN*8 .. warpN*8+7
    // layout stride: per nt = KTAPS*4*256 = 9216 B = 1152 int2
    const int2* wfrag = (const int2*)(g_wfrag + (size_t)(warpN * 8) * (KTAPS * 4 * 256))
                        + lane;          // + lane*8B

    int acc[2][8][4];
#pragma unroll
    for (int i = 0; i < 2; i++)
#pragma unroll
        for (int j = 0; j < 8; j++)
#pragma unroll
            for (int k = 0; k < 4; k++) acc[i][j][k] = 0;

    asm volatile("cp.async.wait_group 0;\n");
    __syncthreads();      // the ONLY barrier: all slabs visible to all warps

    // ---- mainloop: pure ldmatrix + LDG + mma, no synchronization ----
#pragma unroll 1
    for (int tap = 0; tap < KTAPS; tap++) {
        const uint32_t baseA = smem_u32 + tap * ABUF;
#pragma unroll
        for (int kc = 0; kc < 4; kc++) {
            int a[2][4];
#pragma unroll
            for (int mi = 0; mi < 2; mi++) {
                int row = warpM * 32 + mi * 16 + (lane & 15);
                int col = kc * 32 + ((lane >> 4) << 4);
                uint32_t addr = baseA + row * PA + col;
                asm volatile(
                    "ldmatrix.sync.aligned.m8n8.x4.shared.b16 {%0,%1,%2,%3}, [%4];\n"
                    : "=r"(a[mi][0]), "=r"(a[mi][1]), "=r"(a[mi][2]), "=r"(a[mi][3])
                    : "r"(addr));
            }
            const int2* wp = wfrag + (size_t)(tap * 4 + kc) * 32;  // [tap][kc] block
#pragma unroll
            for (int tn = 0; tn < 8; tn++) {
                int2 f = __ldg(wp + (size_t)tn * 1152);            // nt stride
                mma_s8(acc[0][tn], a[0], f.x, f.y);
                mma_s8(acc[1][tn], a[1], f.x, f.y);
            }
        }
    }

    // ---- epilogue: bias + arithmetic shift + clamp -> float32 out ----
#pragma unroll
    for (int tn = 0; tn < 8; tn++) {
#pragma unroll
        for (int cb = 0; cb < 2; cb++) {
            int ng = warpN * 64 + tn * 8 + 2 * tig + cb;
            int tb = __float2int_rn(__ldg(&tbias[ng]));
            int sh = -__ldg(&nshift[ng]);
            int mn = __ldg(&amin[ng]);
            int mx = __ldg(&amax[ng]);
            float* rowp = out + ((size_t)b * COUT + ng) * HWPix + hw0;
#pragma unroll
            for (int mi = 0; mi < 2; mi++) {
#pragma unroll
                for (int rh = 0; rh < 2; rh++) {
                    int v = acc[mi][tn][rh * 2 + cb];
                    v = (v + tb) >> sh;
                    v = max(mn, min(mx, v));
                    int ml = warpM * 32 + mi * 16 + rh * 8 + g;
                    rowp[ml] = (float)v;
                }
            }
        }
    }
}

// ---------------------------------------------------------------------------
// Launch
// ---------------------------------------------------------------------------
extern "C" void kernel_launch(void* const* d_in, const int* in_sizes, int n_in,
                              void* d_out, int out_size) {
    const float* x      = (const float*)d_in[0];
    const float* weight = (const float*)d_in[1];
    const float* tbias  = (const float*)d_in[2];
    const int*   nsh    = (const int*)d_in[3];
    const int*   amin   = (const int*)d_in[4];
    const int*   amax   = (const int*)d_in[5];
    float* out = (float*)d_out;

    (void)cudaFuncSetAttribute(conv_mma_kernel,
                               cudaFuncAttributeMaxDynamicSharedMemorySize,
                               SMEMSZ);

    convert_kernel<<<536, 256>>>(x, weight);                       // 392 + 144 blocks
    conv_mma_kernel<<<BATCH * (HWPix / 64), 256, SMEMSZ>>>(tbias, nsh, amin, amax, out);
}